// round 16
// baseline (speedup 1.0000x reference)
#include <cuda_runtime.h>
#include <cuda_bf16.h>
#include <cstdint>

#define BB 8
#define LL 4096
#define DM 512
#define HH 8
#define DD 64
#define UU 45
#define NCH 16
#define CHUNK (LL / NCH)
#define SCALE 0.125f
#define BL (BB * LL)

// ---------------- scratch ----------------
__device__ float g_Q[BB * HH * LL * DD];
__device__ float g_K[BB * HH * LL * DD];
__device__ float g_V[BB * HH * LL * DD];
__device__ float g_M[BB * HH * LL];
__device__ int   g_top[BB * HH * UU];
__device__ float g_meanV[BB * HH * DD];
__device__ float g_mvp[32][BB * DM];
__device__ float g_base[BB * DM];
__device__ float g_pm[BB * HH * NCH * UU];
__device__ float g_pl[BB * HH * NCH * UU];
__device__ float g_pacc[BB * HH * NCH * UU * DD];
__device__ float g_attn[BB * HH * UU * DD];
__device__ int g_hitcnt[BB * LL];
__device__ int g_hitlist[BB * LL * 8];
__device__ __align__(16) __nv_bfloat16 g_Wth[3][DM * DM];
__device__ __align__(16) __nv_bfloat16 g_Wtl[3][DM * DM];

// ================= PTX helpers =================
__device__ __forceinline__ uint32_t smem_u32(const void* p) {
    uint32_t a;
    asm("{ .reg .u64 t; cvta.to.shared.u64 t, %1; cvt.u32.u64 %0, t; }"
        : "=r"(a) : "l"(p));
    return a;
}
#define SWZ128(off)   ((off) ^ (((off) >> 3) & 0x70))

#define CP_ASYNC16(dst, src) \
    asm volatile("cp.async.cg.shared.global [%0], [%1], 16;" :: "r"(dst), "l"(src))
#define CP_COMMIT() asm volatile("cp.async.commit_group;" ::: "memory")
#define CP_WAIT(n)  asm volatile("cp.async.wait_group %0;" :: "n"(n) : "memory")

__device__ __forceinline__ void ldsm_x4(uint32_t* r, uint32_t addr) {
    asm volatile("ldmatrix.sync.aligned.m8n8.x4.shared.b16 {%0,%1,%2,%3}, [%4];"
        : "=r"(r[0]), "=r"(r[1]), "=r"(r[2]), "=r"(r[3]) : "r"(addr));
}
__device__ __forceinline__ void mma16816(float* d, const uint32_t* a,
                                         const uint32_t* b, const float* c) {
    asm volatile(
        "mma.sync.aligned.m16n8k16.row.col.f32.bf16.bf16.f32 "
        "{%0,%1,%2,%3},{%4,%5,%6,%7},{%8,%9},{%10,%11,%12,%13};"
        : "=f"(d[0]), "=f"(d[1]), "=f"(d[2]), "=f"(d[3])
        : "r"(a[0]), "r"(a[1]), "r"(a[2]), "r"(a[3]),
          "r"(b[0]), "r"(b[1]),
          "f"(c[0]), "f"(c[1]), "f"(c[2]), "f"(c[3]));
}

__device__ __forceinline__ void split8(const float* xs, __nv_bfloat16* h,
                                       __nv_bfloat16* l) {
#pragma unroll
    for (int i = 0; i < 8; i++) {
        __nv_bfloat16 hb = __float2bfloat16(xs[i]);
        h[i] = hb;
        l[i] = __float2bfloat16(xs[i] - __bfloat162float(hb));
    }
}
__device__ __forceinline__ uint32_t pack2(float a, float b) {
    __nv_bfloat162 v;
    v.x = __float2bfloat16(a);
    v.y = __float2bfloat16(b);
    return *(uint32_t*)&v;
}

#define T_AH 0
#define T_AL 16384
#define T_WH 32768
#define T_WL 49152
#define STAGE_SZ 65536
#define OFF_BIAS 131072
#define DYN_SMEM (131072 + 1024)

// att_mma smem offsets
#define A_QH 0
#define A_QL 8192
#define A_KH 16384
#define A_KL 24576
#define A_VH 32768
#define A_VL 40960
#define A_TOP 49152
#define DYN_SMEM_ATT (49152 + 256)

// ---------------- W prep: transpose + split to bf16 hi/lo ----------------
__global__ __launch_bounds__(256) void prep_w(const float* __restrict__ Wq,
                                              const float* __restrict__ Wk,
                                              const float* __restrict__ Wv)
{
    int which = blockIdx.y;
    const float* W = (which == 0) ? Wq : (which == 1) ? Wk : Wv;
    int idx = (blockIdx.x * 256 + threadIdx.x) * 4;
    int n = idx >> 9, k = idx & 511;
#pragma unroll
    for (int i = 0; i < 4; i++) {
        float x = W[(size_t)(k + i) * DM + n];
        __nv_bfloat16 hb = __float2bfloat16(x);
        g_Wth[which][(size_t)n * DM + k + i] = hb;
        g_Wtl[which][(size_t)n * DM + k + i] = __float2bfloat16(x - __bfloat162float(hb));
    }
}

// ---------------- split-bf16 mma.sync GEMM with fused fp32->bf16 A split ----------------
__global__ __launch_bounds__(256) void proj_mma(
    const float* __restrict__ qin, const float* __restrict__ kin,
    const float* __restrict__ vin,
    const float* __restrict__ bq, const float* __restrict__ bk,
    const float* __restrict__ bv)
{
    extern __shared__ char dsm[];
    int which = blockIdx.z;
    float* P = (which == 0) ? g_Q : (which == 1) ? g_K : g_V;
    const float* bias = (which == 0) ? bq : (which == 1) ? bk : bv;
    const float* Afp = (which == 0) ? qin : (which == 1) ? kin : vin;
    const __nv_bfloat16* Wh = g_Wth[which];
    const __nv_bfloat16* Wl = g_Wtl[which];

    uint32_t su = smem_u32(dsm);
    int tid = threadIdx.x;
    int lane = tid & 31, wid = tid >> 5;
    int wm = wid & 3, wn = wid >> 2;
    int m0 = blockIdx.y * 128, n0 = blockIdx.x * 128;

    float* bias_s = (float*)(dsm + OFF_BIAS);
    if (tid < 128) bias_s[tid] = bias[n0 + tid];

    float acc[2][8][4];
#pragma unroll
    for (int a = 0; a < 2; a++)
#pragma unroll
        for (int b = 0; b < 8; b++)
#pragma unroll
            for (int c = 0; c < 4; c++) acc[a][b][c] = 0.f;

    float4 areg[4][2];
    auto ldA = [&](int k0) {
#pragma unroll
        for (int t = 0; t < 4; t++) {
            int idx = tid + 256 * t;
            int r = idx >> 3, c = idx & 7;
            const float* src = Afp + (size_t)(m0 + r) * DM + k0 + c * 8;
            areg[t][0] = *(const float4*)src;
            areg[t][1] = *(const float4*)(src + 4);
        }
    };
    auto stsA = [&](int stage) {
#pragma unroll
        for (int t = 0; t < 4; t++) {
            int idx = tid + 256 * t;
            int r = idx >> 3, c = idx & 7;
            float xs[8] = {areg[t][0].x, areg[t][0].y, areg[t][0].z, areg[t][0].w,
                           areg[t][1].x, areg[t][1].y, areg[t][1].z, areg[t][1].w};
            __align__(16) __nv_bfloat16 h[8], l[8];
            split8(xs, h, l);
            uint32_t sw = SWZ128((uint32_t)(r * 128 + c * 16));
            *(uint4*)(dsm + stage * STAGE_SZ + T_AH + sw) = *(uint4*)h;
            *(uint4*)(dsm + stage * STAGE_SZ + T_AL + sw) = *(uint4*)l;
        }
    };
    auto cpW = [&](int stage, int k0) {
        uint32_t sb = su + stage * STAGE_SZ;
#pragma unroll
        for (int t = 0; t < 4; t++) {
            int idx = tid + 256 * t;
            int r = idx >> 3, c = idx & 7;
            uint32_t sw = SWZ128((uint32_t)(r * 128 + c * 16));
            CP_ASYNC16(sb + T_WH + sw, Wh + (size_t)(n0 + r) * DM + k0 + c * 8);
            CP_ASYNC16(sb + T_WL + sw, Wl + (size_t)(n0 + r) * DM + k0 + c * 8);
        }
        CP_COMMIT();
    };

    ldA(0);
    cpW(0, 0);
    stsA(0);
    ldA(64);

    int a_row = (lane & 15), a_k16 = (lane >> 4) << 4;
    int b_grp = lane >> 3;
    int b_row = ((b_grp >> 1) << 3) + (lane & 7);
    int b_k16 = (b_grp & 1) << 4;

    for (int chunk = 0; chunk < 8; chunk++) {
        if (chunk < 7) cpW((chunk + 1) & 1, (chunk + 1) * 64);
        if (chunk < 7) { CP_WAIT(1); } else { CP_WAIT(0); }
        __syncthreads();

        if (chunk < 7) stsA((chunk + 1) & 1);
        if (chunk < 6) ldA((chunk + 2) * 64);

        uint32_t sb = su + (chunk & 1) * STAGE_SZ;
#pragma unroll
        for (int ks = 0; ks < 4; ks++) {
            uint32_t ah[2][4], al[2][4], bh[16], bl[16];
#pragma unroll
            for (int mf = 0; mf < 2; mf++) {
                int row = wm * 32 + mf * 16 + a_row;
                uint32_t off = SWZ128((uint32_t)(row * 128 + ks * 32 + a_k16));
                ldsm_x4(ah[mf], sb + T_AH + off);
                ldsm_x4(al[mf], sb + T_AL + off);
            }
#pragma unroll
            for (int g2 = 0; g2 < 4; g2++) {
                int row = wn * 64 + g2 * 16 + b_row;
                uint32_t off = SWZ128((uint32_t)(row * 128 + ks * 32 + b_k16));
                ldsm_x4(&bh[g2 * 4], sb + T_WH + off);
                ldsm_x4(&bl[g2 * 4], sb + T_WL + off);
            }
#pragma unroll
            for (int mf = 0; mf < 2; mf++)
#pragma unroll
                for (int nf = 0; nf < 8; nf++)
                    mma16816(acc[mf][nf], ah[mf], &bh[nf * 2], acc[mf][nf]);
#pragma unroll
            for (int mf = 0; mf < 2; mf++)
#pragma unroll
                for (int nf = 0; nf < 8; nf++)
                    mma16816(acc[mf][nf], ah[mf], &bl[nf * 2], acc[mf][nf]);
#pragma unroll
            for (int mf = 0; mf < 2; mf++)
#pragma unroll
                for (int nf = 0; nf < 8; nf++)
                    mma16816(acc[mf][nf], al[mf], &bh[nf * 2], acc[mf][nf]);
        }
        __syncthreads();
    }

    float* Cs = (float*)dsm;
#pragma unroll
    for (int mf = 0; mf < 2; mf++)
#pragma unroll
        for (int nf = 0; nf < 8; nf++) {
            int r = wm * 32 + mf * 16 + (lane >> 2);
            int col = wn * 64 + nf * 8 + (lane & 3) * 2;
            Cs[r * 132 + col]           = acc[mf][nf][0] + bias_s[col];
            Cs[r * 132 + col + 1]       = acc[mf][nf][1] + bias_s[col + 1];
            Cs[(r + 8) * 132 + col]     = acc[mf][nf][2] + bias_s[col];
            Cs[(r + 8) * 132 + col + 1] = acc[mf][nf][3] + bias_s[col + 1];
        }
    __syncthreads();

    // fused meanV partial: column sums of the V tile (deterministic order)
    if (which == 2 && tid < 128) {
        float s = 0.f;
#pragma unroll 8
        for (int r = 0; r < 128; r++) s += Cs[r * 132 + tid];
        int b = m0 >> 12, mt = (m0 >> 7) & 31;
        g_mvp[mt][b * DM + n0 + tid] = s;
    }

#pragma unroll
    for (int it = 0; it < 16; it++) {
        int idx = tid + it * 256;
        int row = idx >> 5, c4 = idx & 31;
        int m = m0 + row;
        int b = m >> 12, l = m & (LL - 1);
        int n = n0 + c4 * 4;
        int h = n >> 6, d = n & 63;
        float4 v;
        v.x = Cs[row * 132 + c4 * 4 + 0];
        v.y = Cs[row * 132 + c4 * 4 + 1];
        v.z = Cs[row * 132 + c4 * 4 + 2];
        v.w = Cs[row * 132 + c4 * 4 + 3];
        *(float4*)&P[((size_t)(b * HH + h) * LL + l) * DD + d] = v;
    }
}

// ---------------- sampled scoring via MMA: 128x48x64 per block ----------------
__global__ __launch_bounds__(128) void score_mma(const int* __restrict__ sidx)
{
    __shared__ __align__(16) char AH[16384];
    __shared__ __align__(16) char AL[16384];
    __shared__ __align__(16) char BHs[6144];
    __shared__ __align__(16) char BLs[6144];
    __shared__ int ssi[UU];
    int bh = blockIdx.x, m0 = blockIdx.y * 128;
    int tid = threadIdx.x, lane = tid & 31, wm = tid >> 5;

    if (tid < UU) ssi[tid] = sidx[tid];
    for (int i = tid; i < 6144 / 16; i += 128) {
        ((uint4*)BHs)[i] = make_uint4(0, 0, 0, 0);
        ((uint4*)BLs)[i] = make_uint4(0, 0, 0, 0);
    }
    __syncthreads();

    for (int u = tid; u < UU * 8; u += 128) {
        int j = u >> 3, c = u & 7;
        const float* src = g_K + ((size_t)bh * LL + ssi[j]) * DD + c * 8;
        float4 f0 = *(const float4*)src, f1 = *(const float4*)(src + 4);
        float xs[8] = {f0.x, f0.y, f0.z, f0.w, f1.x, f1.y, f1.z, f1.w};
        __align__(16) __nv_bfloat16 h[8], l[8];
        split8(xs, h, l);
        uint32_t sw = SWZ128((uint32_t)(j * 128 + c * 16));
        *(uint4*)(BHs + sw) = *(uint4*)h;
        *(uint4*)(BLs + sw) = *(uint4*)l;
    }
#pragma unroll
    for (int t = 0; t < 8; t++) {
        int idx = tid + 128 * t;
        int r = idx >> 3, c = idx & 7;
        const float* src = g_Q + ((size_t)bh * LL + m0 + r) * DD + c * 8;
        float4 f0 = *(const float4*)src, f1 = *(const float4*)(src + 4);
        float xs[8] = {f0.x, f0.y, f0.z, f0.w, f1.x, f1.y, f1.z, f1.w};
        __align__(16) __nv_bfloat16 h[8], l[8];
        split8(xs, h, l);
        uint32_t sw = SWZ128((uint32_t)(r * 128 + c * 16));
        *(uint4*)(AH + sw) = *(uint4*)h;
        *(uint4*)(AL + sw) = *(uint4*)l;
    }
    __syncthreads();

    float acc[2][6][4];
#pragma unroll
    for (int a = 0; a < 2; a++)
#pragma unroll
        for (int b = 0; b < 6; b++)
#pragma unroll
            for (int c = 0; c < 4; c++) acc[a][b][c] = 0.f;

    uint32_t suA_h = smem_u32(AH), suA_l = smem_u32(AL);
    uint32_t suB_h = smem_u32(BHs), suB_l = smem_u32(BLs);
    int a_row = (lane & 15), a_k16 = (lane >> 4) << 4;
    int b_grp = lane >> 3;
    int b_row = ((b_grp >> 1) << 3) + (lane & 7);
    int b_k16 = (b_grp & 1) << 4;

#pragma unroll
    for (int ks = 0; ks < 4; ks++) {
        uint32_t ah[2][4], al[2][4], bhf[12], blf[12];
#pragma unroll
        for (int mf = 0; mf < 2; mf++) {
            int row = wm * 32 + mf * 16 + a_row;
            uint32_t off = SWZ128((uint32_t)(row * 128 + ks * 32 + a_k16));
            ldsm_x4(ah[mf], suA_h + off);
            ldsm_x4(al[mf], suA_l + off);
        }
#pragma unroll
        for (int g2 = 0; g2 < 3; g2++) {
            int row = g2 * 16 + b_row;
            uint32_t off = SWZ128((uint32_t)(row * 128 + ks * 32 + b_k16));
            ldsm_x4(&bhf[g2 * 4], suB_h + off);
            ldsm_x4(&blf[g2 * 4], suB_l + off);
        }
#pragma unroll
        for (int mf = 0; mf < 2; mf++)
#pragma unroll
            for (int nf = 0; nf < 6; nf++)
                mma16816(acc[mf][nf], ah[mf], &bhf[nf * 2], acc[mf][nf]);
#pragma unroll
        for (int mf = 0; mf < 2; mf++)
#pragma unroll
            for (int nf = 0; nf < 6; nf++)
                mma16816(acc[mf][nf], ah[mf], &blf[nf * 2], acc[mf][nf]);
#pragma unroll
        for (int mf = 0; mf < 2; mf++)
#pragma unroll
            for (int nf = 0; nf < 6; nf++)
                mma16816(acc[mf][nf], al[mf], &bhf[nf * 2], acc[mf][nf]);
    }

    int cbase = (lane & 3) * 2;
#pragma unroll
    for (int mf = 0; mf < 2; mf++) {
        float mx0 = -1e30f, sm0 = 0.f, mx1 = -1e30f, sm1 = 0.f;
#pragma unroll
        for (int nf = 0; nf < 6; nf++) {
            int c0 = nf * 8 + cbase, c1 = c0 + 1;
            if (c0 < UU) { mx0 = fmaxf(mx0, acc[mf][nf][0]); sm0 += acc[mf][nf][0]; }
            if (c1 < UU) { mx0 = fmaxf(mx0, acc[mf][nf][1]); sm0 += acc[mf][nf][1]; }
            if (c0 < UU) { mx1 = fmaxf(mx1, acc[mf][nf][2]); sm1 += acc[mf][nf][2]; }
            if (c1 < UU) { mx1 = fmaxf(mx1, acc[mf][nf][3]); sm1 += acc[mf][nf][3]; }
        }
#pragma unroll
        for (int off = 1; off < 4; off <<= 1) {
            mx0 = fmaxf(mx0, __shfl_xor_sync(0xffffffffu, mx0, off));
            sm0 += __shfl_xor_sync(0xffffffffu, sm0, off);
            mx1 = fmaxf(mx1, __shfl_xor_sync(0xffffffffu, mx1, off));
            sm1 += __shfl_xor_sync(0xffffffffu, sm1, off);
        }
        if ((lane & 3) == 0) {
            int r = wm * 32 + mf * 16 + (lane >> 2);
            g_M[(size_t)bh * LL + m0 + r]     = (mx0 - sm0 * (1.f / UU)) * SCALE;
            g_M[(size_t)bh * LL + m0 + r + 8] = (mx1 - sm1 * (1.f / UU)) * SCALE;
        }
    }
}

// ---------------- top-45 via radix select ----------------
__global__ __launch_bounds__(256) void topk_kernel()
{
    __shared__ uint32_t uvals[LL];
    __shared__ int histw[8][256];
    __shared__ int scan[256];
    __shared__ int sel_byte, new_k;
    __shared__ int cnt_g, cnt_e;
    __shared__ int eq[256];
    int bh = blockIdx.x, tid = threadIdx.x;
    int w = tid >> 5;

    for (int i = tid; i < LL; i += 256) {
        uint32_t u = __float_as_uint(g_M[(size_t)bh * LL + i]);
        uvals[i] = (u & 0x80000000u) ? ~u : (u | 0x80000000u);
    }

    uint32_t prefix = 0, mask = 0;
    int k = UU;
    for (int pass = 0; pass < 4; pass++) {
        int shift = 24 - pass * 8;
#pragma unroll
        for (int ww = 0; ww < 8; ww++) histw[ww][tid] = 0;
        __syncthreads();
        for (int i = tid; i < LL; i += 256) {
            uint32_t u = uvals[i];
            if ((u & mask) == prefix)
                atomicAdd(&histw[w][(u >> shift) & 255], 1);
        }
        __syncthreads();
        int c = 0;
#pragma unroll
        for (int ww = 0; ww < 8; ww++) c += histw[ww][tid];
        scan[tid] = c;
        __syncthreads();
#pragma unroll
        for (int off = 1; off < 256; off <<= 1) {
            int v = (tid + off < 256) ? scan[tid + off] : 0;
            __syncthreads();
            scan[tid] += v;
            __syncthreads();
        }
        {
            int snext = (tid < 255) ? scan[tid + 1] : 0;
            if (scan[tid] >= k && snext < k) {
                sel_byte = tid;
                new_k = k - snext;
            }
        }
        __syncthreads();
        prefix |= ((uint32_t)sel_byte << shift);
        mask |= (255u << shift);
        k = new_k;
        __syncthreads();
    }
    uint32_t T = prefix;

    if (tid == 0) { cnt_g = 0; cnt_e = 0; }
    __syncthreads();
    for (int i = tid; i < LL; i += 256) {
        uint32_t u = uvals[i];
        if (u > T) {
            int p = atomicAdd(&cnt_g, 1);
            g_top[bh * UU + p] = i;
        } else if (u == T) {
            int p = atomicAdd(&cnt_e, 1);
            if (p < 256) eq[p] = i;
        }
    }
    __syncthreads();
    int ng = cnt_g;
    int need = UU - ng;
    if (tid == 0 && need > 0) {
        if (cnt_e <= 256) {
            int ec = cnt_e;
            for (int s = 0; s < need; s++) {
                int best = s;
                for (int j = s + 1; j < ec; j++)
                    if (eq[j] < eq[best]) best = j;
                int t = eq[s]; eq[s] = eq[best]; eq[best] = t;
                g_top[bh * UU + ng + s] = eq[s];
            }
        } else {
            int got = 0;
            for (int i = 0; i < LL && got < need; i++)
                if (uvals[i] == T) { g_top[bh * UU + ng + got] = i; got++; }
        }
    }
}

// ---------------- hit map ----------------
__global__ __launch_bounds__(256) void zero_hits()
{
    int i = blockIdx.x * 256 + threadIdx.x;
    g_hitcnt[i] = 0;
}
__global__ __launch_bounds__(64) void build_hits()
{
    int bh = blockIdx.x, tid = threadIdx.x;
    if (tid < UU) {
        int b = bh >> 3, h = bh & 7;
        int t = g_top[bh * UU + tid];
        int p = atomicAdd(&g_hitcnt[b * LL + t], 1);
        g_hitlist[(b * LL + t) * 8 + p] = (h << 8) | tid;
    }
}

// ---------------- meanV reduce from proj partials ----------------
__global__ __launch_bounds__(64) void mv_reduce()
{
    int bh = blockIdx.x, d = threadIdx.x;
    int b = bh >> 3, h = bh & 7;
    float s = 0.f;
#pragma unroll
    for (int p = 0; p < 32; p++) s += g_mvp[p][b * DM + h * 64 + d];
    g_meanV[bh * DD + d] = s * (1.f / LL);
}

// ---------------- base row per batch ----------------
__global__ __launch_bounds__(512) void base_kernel(const float* __restrict__ Wo,
                                                   const float* __restrict__ bo)
{
    int b = blockIdx.x, c = threadIdx.x;
    float acc = bo[c];
    const float* mv = g_meanV + b * DM;
    for (int k = 0; k < DM; k++) acc += mv[k] * Wo[(size_t)k * DM + c];
    g_base[b * DM + c] = acc;
}

// ---------------- flash attention via MMA, split over NCH chunks ----------------
__global__ __launch_bounds__(128) void att_mma()
{
    extern __shared__ char sm[];
    int bh = blockIdx.x, ch = blockIdx.y;
    int tid = threadIdx.x, lane = tid & 31, w = tid >> 5;
    int* tops = (int*)(sm + A_TOP);

    if (tid < UU) tops[tid] = g_top[bh * UU + tid];
    for (int i = tid; i < 1024; i += 128) {
        ((uint4*)(sm + A_QH))[i] = make_uint4(0, 0, 0, 0);
        ((uint4*)(sm + A_QL))[i] = make_uint4(0, 0, 0, 0);
    }
    __syncthreads();
    for (int u = tid; u < UU * 8; u += 128) {
        int j = u >> 3, c = u & 7;
        const float* src = g_Q + ((size_t)bh * LL + tops[j]) * DD + c * 8;
        float4 f0 = *(const float4*)src, f1 = *(const float4*)(src + 4);
        float xs[8] = {f0.x, f0.y, f0.z, f0.w, f1.x, f1.y, f1.z, f1.w};
        __align__(16) __nv_bfloat16 h[8], l[8];
        split8(xs, h, l);
        uint32_t sw = SWZ128((uint32_t)(j * 128 + c * 16));
        *(uint4*)(sm + A_QH + sw) = *(uint4*)h;
        *(uint4*)(sm + A_QL + sw) = *(uint4*)l;
    }
    __syncthreads();

    uint32_t su = smem_u32(sm);
    int a_row = (lane & 15), a_k16 = (lane >> 4) << 4;
    int b_grp = lane >> 3;
    int b_row = ((b_grp >> 1) << 3) + (lane & 7);
    int b_k16 = (b_grp & 1) << 4;

    uint32_t qah[4][4], qal[4][4];
#pragma unroll
    for (int ks = 0; ks < 4; ks++) {
        int row = w * 16 + a_row;
        uint32_t off = SWZ128((uint32_t)(row * 128 + ks * 32 + a_k16));
        ldsm_x4(qah[ks], su + A_QH + off);
        ldsm_x4(qal[ks], su + A_QL + off);
    }

    float mrow[2] = {-1e30f, -1e30f};
    float lsum[2] = {0.f, 0.f};
    float oacc[8][4];
#pragma unroll
    for (int nf = 0; nf < 8; nf++)
#pragma unroll
        for (int c = 0; c < 4; c++) oacc[nf][c] = 0.f;

    int key0 = ch * CHUNK;
    for (int t0 = 0; t0 < CHUNK; t0 += 64) {
        __syncthreads();
        for (int i = tid; i < 1024; i += 128) {
            int r = i >> 4, c4 = i & 15;
            const float* ks_ = g_K + ((size_t)bh * LL + key0 + t0 + r) * DD + c4 * 4;
            float4 kv = *(const float4*)ks_;
            float xk[4] = {kv.x, kv.y, kv.z, kv.w};
            __nv_bfloat16 h4[4], l4[4];
#pragma unroll
            for (int q2 = 0; q2 < 4; q2++) {
                __nv_bfloat16 hb = __float2bfloat16(xk[q2]);
                h4[q2] = hb;
                l4[q2] = __float2bfloat16(xk[q2] - __bfloat162float(hb));
            }
            uint32_t sw = SWZ128((uint32_t)(r * 128 + c4 * 8));
            *(uint2*)(sm + A_KH + sw) = *(uint2*)h4;
            *(uint2*)(sm + A_KL + sw) = *(uint2*)l4;

            const float* vs_ = g_V + ((size_t)bh * LL + key0 + t0 + r) * DD + c4 * 4;
            float4 vv = *(const float4*)vs_;
            float xv[4] = {vv.x, vv.y, vv.z, vv.w};
#pragma unroll
            for (int q2 = 0; q2 < 4; q2++) {
                int d = c4 * 4 + q2;
                __nv_bfloat16 hb = __float2bfloat16(xv[q2]);
                __nv_bfloat16 lb = __float2bfloat16(xv[q2] - __bfloat162float(hb));
                uint32_t swv = SWZ128((uint32_t)(d * 128 + r * 2));
                *(__nv_bfloat16*)(sm + A_VH + swv) = hb;
                *(__nv_bfloat16*)(sm + A_VL + swv) = lb;
            }
        }
        __syncthreads();

        float sacc[8][4];
#pragma unroll
        for (int nf = 0; nf < 8; nf++)
#pragma unroll
            for (int c = 0; c < 4; c++) sacc[nf][c] = 0.f;
#pragma unroll
        for (int ks = 0; ks < 4; ks++) {
            uint32_t kbh[16], kbl[16];
#pragma unroll
            for (int g2 = 0; g2 < 4; g2++) {
                int row = g2 * 16 + b_row;
                uint32_t off = SWZ128((uint32_t)(row * 128 + ks * 32 + b_k16));
                ldsm_x4(&kbh[g2 * 4], su + A_KH + off);
                ldsm_x4(&kbl[g2 * 4], su + A_KL + off);
            }
#pragma unroll
            for (int nf = 0; nf < 8; nf++)
                mma16816(sacc[nf], qah[ks], &kbh[nf * 2], sacc[nf]);
#pragma unroll
            for (int nf = 0; nf < 8; nf++)
                mma16816(sacc[nf], qah[ks], &kbl[nf * 2], sacc[nf]);
#pragma unroll
            for (int nf = 0; nf < 8; nf++)
                mma16816(sacc[nf], qal[ks], &kbh[nf * 2], sacc[nf]);
        }
#pragma unroll
        for (int nf = 0; nf < 8; nf++)
#pragma unroll
            for (int c = 0; c < 4; c++) sacc[nf][c] *= SCALE;
        float tmax0 = -1e30f, tmax1 = -1e30f;
#pragma unroll
        for (int nf = 0; nf < 8; nf++) {
            tmax0 = fmaxf(tmax0, fmaxf(sacc[nf][0], sacc[nf][1]));
            tmax1 = fmaxf(tmax1, fmaxf(sacc[nf][2], sacc[nf][3]));
        }
#pragma unroll
        for (int off = 1; off < 4; off <<= 1) {
            tmax0 = fmaxf(tmax0, __shfl_xor_sync(0xffffffffu, tmax0, off));
            tmax1 = fmaxf(tmax1, __shfl_xor_sync(0xffffffffu, tmax1, off));
        }
        float mn0 = fmaxf(mrow[0], tmax0), mn1 = fmaxf(mrow[1], tmax1);
        float al0 = __expf(mrow[0] - mn0), al1 = __expf(mrow[1] - mn1);
        float rs0 = 0.f, rs1 = 0.f;
#pragma unroll
        for (int nf = 0; nf < 8; nf++) {
            sacc[nf][0] = __expf(sacc[nf][0] - mn0);
            sacc[nf][1] = __expf(sacc[nf][1] - mn0);
            sacc[nf][2] = __expf(sacc[nf][2] - mn1);
            sacc[nf][3] = __expf(sacc[nf][3] - mn1);
            rs0 += sacc[nf][0] + sacc[nf][1];
            rs1 += sacc[nf][2] + sacc[nf][3];
        }
#pragma unroll
        for (int off = 1; off < 4; off <<= 1) {
            rs0 += __shfl_xor_sync(0xffffffffu, rs0, off);
            rs1 += __shfl_xor_sync(0xffffffffu, rs1, off);
        }
        lsum[0] = lsum[0] * al0 + rs0;
        lsum[1] = lsum[1] * al1 + rs1;
        mrow[0] = mn0;
        mrow[1] = mn1;
#pragma unroll
        for (int nf = 0; nf < 8; nf++) {
            oacc[nf][0] *= al0; oacc[nf][1] *= al0;
            oacc[nf][2] *= al1; oacc[nf][3] *= al1;
        }
#pragma unroll
        for (int ks = 0; ks < 4; ks++) {
            uint32_t pah[4], pal[4];
            {
                float p0 = sacc[2 * ks][0],     p1 = sacc[2 * ks][1];
                float p2 = sacc[2 * ks][2],     p3 = sacc[2 * ks][3];
                float p4 = sacc[2 * ks + 1][0], p5 = sacc[2 * ks + 1][1];
                float p6 = sacc[2 * ks + 1][2], p7 = sacc[2 * ks + 1][3];
                float h0 = __bfloat162float(__float2bfloat16(p0));
                float h1 = __bfloat162float(__float2bfloat16(p1));
                float h2 = __bfloat162float(__float2bfloat16(p2));
                float h3 = __bfloat162float(__float2bfloat16(p3));
                float h4 = __bfloat162float(__float2bfloat16(p4));
                float h5 = __bfloat162float(__float2bfloat16(p5));
                float h6 = __bfloat162float(__float2bfloat16(p6));
                float h7 = __bfloat162float(__float2bfloat16(p7));
                pah[0] = pack2(p0, p1); pah[1] = pack2(p2, p3);
                pah[2] = pack2(p4, p5); pah[3] = pack2(p6, p7);
                pal[0] = pack2(p0 - h0, p1 - h1); pal[1] = pack2(p2 - h2, p3 - h3);
                pal[2] = pack2(p4 - h4, p5 - h5); pal[3] = pack2(p6 - h6, p7 - h7);
            }
            uint32_t vbh[16], vbl[16];
#pragma unroll
            for (int g2 = 0; g2 < 4; g2++) {
                int row = g2 * 16 + b_row;
                uint32_t off = SWZ128((uint32_t)(row * 128 + ks * 32 + b_k16));
                ldsm_x4(&vbh[g2 * 4], su + A_VH + off);
                ldsm_x4(&vbl[g2 * 4], su + A_VL + off);
            }
#pragma unroll
            for (int nf = 0; nf < 8; nf++)
                mma16816(oacc[nf], pah, &vbh[nf * 2], oacc[nf]);
#pragma unroll
            for (int nf = 0; nf < 8; nf++)
                mma16816(oacc[nf], pah, &vbl[nf * 2], oacc[nf]);
#pragma unroll
            for (int nf = 0; nf < 8; nf++)
                mma16816(oacc[nf], pal, &vbh[nf * 2], oacc[nf]);
        }
    }

    int r0 = w * 16 + (lane >> 2);
    int r1 = r0 + 8;
    int cb = (lane & 3) * 2;
    if (r0 < UU) {
        int idx = (bh * NCH + ch) * UU + r0;
        if ((lane & 3) == 0) { g_pm[idx] = mrow[0]; g_pl[idx] = lsum[0]; }
        float* pa = g_pacc + (size_t)idx * DD;
#pragma unroll
        for (int nf = 0; nf < 8; nf++) {
            pa[nf * 8 + cb]     = oacc[nf][0];
            pa[nf * 8 + cb + 1] = oacc[nf][1];
        }
    }
    if (r1 < UU) {
        int idx = (bh * NCH + ch) * UU + r1;
        if ((lane & 3) == 0) { g_pm[idx] = mrow[1]; g_pl[idx] = lsum[1]; }
        float* pa = g_pacc + (size_t)idx * DD;
#pragma unroll
        for (int nf = 0; nf < 8; nf++) {
            pa[nf * 8 + cb]     = oacc[nf][2];
            pa[nf * 8 + cb + 1] = oacc[nf][3];
        }
    }
}

// ---------------- merge split-L partials ----------------
__global__ __launch_bounds__(64) void combine_kernel()
{
    int r = blockIdx.x;
    int d = threadIdx.x;
    int bh = r / UU, q = r % UU;
    float M = -1e30f;
#pragma unroll
    for (int c = 0; c < NCH; c++)
        M = fmaxf(M, g_pm[(bh * NCH + c) * UU + q]);
    float Ltot = 0.f, acc = 0.f;
#pragma unroll
    for (int c = 0; c < NCH; c++) {
        int idx = (bh * NCH + c) * UU + q;
        float e = __expf(g_pm[idx] - M);
        Ltot += g_pl[idx] * e;
        acc  += e * g_pacc[(size_t)idx * DD + d];
    }
    g_attn[(size_t)(bh * UU + q) * DD + d] = acc / Ltot;
}

// ---------------- final output: 4 rows/block, hit-list driven ----------------
__global__ __launch_bounds__(128) void final_kernel4(const float* __restrict__ Wo,
                                                     float* __restrict__ out)
{
    __shared__ float delta[64];
    __shared__ int allh[32];
    __shared__ int total_s;
    int q0 = blockIdx.x * 4, b = blockIdx.y;
    int tid = threadIdx.x;
    int c0 = tid * 4;

    if (tid == 0) {
        int t = 0;
        for (int r = 0; r < 4; r++) {
            int c = g_hitcnt[b * LL + q0 + r];
            for (int i = 0; i < c; i++)
                allh[t++] = (r << 16) | g_hitlist[(b * LL + q0 + r) * 8 + i];
        }
        for (int s = 1; s < t; s++) {            // sort by (row, head) asc
            int v = allh[s], j = s;
            while (j > 0 && allh[j - 1] > v) { allh[j] = allh[j - 1]; j--; }
            allh[j] = v;
        }
        total_s = t;
    }
    __syncthreads();
    int total = total_s;

    float4 bsv = *(const float4*)&g_base[b * DM + c0];
    float4 acc[4] = {bsv, bsv, bsv, bsv};

    for (int i = 0; i < total; i++) {
        int e = allh[i];
        int r = e >> 16, h = (e >> 8) & 255, j = e & 255;
        if (tid < 64)
            delta[tid] = g_attn[((size_t)(b * HH + h) * UU + j) * DD + tid] -
                         g_meanV[(b * HH + h) * DD + tid];
        __syncthreads();
#pragma unroll 4
        for (int d = 0; d < 64; d++) {
            float dv = delta[d];
            float4 w = *(const float4*)&Wo[(size_t)(h * 64 + d) * DM + c0];
            acc[r].x += dv * w.x; acc[r].y += dv * w.y;
            acc[r].z += dv * w.z; acc[r].w += dv * w.w;
        }
        __syncthreads();
    }
#pragma unroll
    for (int r = 0; r < 4; r++)
        *(float4*)&out[((size_t)b * LL + q0 + r) * DM + c0] = acc[r];
}

// ---------------- launcher ----------------
extern "C" void kernel_launch(void* const* d_in, const int* in_sizes, int n_in,
                              void* d_out, int out_size)
{
    const float* queries = (const float*)d_in[0];
    const float* keys    = (const float*)d_in[1];
    const float* values  = (const float*)d_in[2];
    const int*   sidx    = (const int*)d_in[3];
    const float* Wq = (const float*)d_in[4];
    const float* bq = (const float*)d_in[5];
    const float* Wk = (const float*)d_in[6];
    const float* bk = (const float*)d_in[7];
    const float* Wv = (const float*)d_in[8];
    const float* bv = (const float*)d_in[9];
    const float* Wo = (const float*)d_in[10];
    const float* bo = (const float*)d_in[11];
    float* out = (float*)d_out;

    static int smem_set = 0;
    if (!smem_set) {
        cudaFuncSetAttribute(proj_mma, cudaFuncAttributeMaxDynamicSharedMemorySize, DYN_SMEM);
        cudaFuncSetAttribute(att_mma, cudaFuncAttributeMaxDynamicSharedMemorySize, DYN_SMEM_ATT);
        smem_set = 1;
    }

    prep_w<<<dim3(256, 3), 256>>>(Wq, Wk, Wv);
    zero_hits<<<BB * LL / 256, 256>>>();

    proj_mma<<<dim3(DM / 128, BL / 128, 3), 256, DYN_SMEM>>>(
        queries, keys, values, bq, bk, bv);

    mv_reduce<<<BB * HH, 64>>>();
    score_mma<<<dim3(BB * HH, LL / 128), 128>>>(sidx);
    topk_kernel<<<BB * HH, 256>>>();
    build_hits<<<BB * HH, 64>>>();
    base_kernel<<<BB, 512>>>(Wo, bo);
    att_mma<<<dim3(BB * HH, NCH), 128, DYN_SMEM_ATT>>>();
    combine_kernel<<<BB * HH * UU, 64>>>();
    final_kernel4<<<dim3(LL / 4, BB), 128>>>(Wo, out);
}

// round 17
// speedup vs baseline: 1.0366x; 1.0366x over previous
#include <cuda_runtime.h>
#include <cuda_bf16.h>
#include <cstdint>

#define BB 8
#define LL 4096
#define DM 512
#define HH 8
#define DD 64
#define UU 45
#define NCH 16
#define CHUNK (LL / NCH)
#define SCALE 0.125f
#define BL (BB * LL)

// ---------------- scratch ----------------
__device__ float g_Q[BB * HH * LL * DD];
__device__ float g_K[BB * HH * LL * DD];
__device__ float g_V[BB * HH * LL * DD];
__device__ float g_M[BB * HH * LL];
__device__ int   g_top[BB * HH * UU];
__device__ float g_meanV[BB * HH * DD];
__device__ float g_mvp[32][BB * DM];
__device__ float g_base[BB * DM];
__device__ float g_pm[BB * HH * NCH * UU];
__device__ float g_pl[BB * HH * NCH * UU];
__device__ float g_pacc[BB * HH * NCH * UU * DD];
__device__ float g_attn[BB * HH * UU * DD];
__device__ int g_hitcnt[BB * LL];
__device__ int g_hitlist[BB * LL * 8];
__device__ __align__(16) __nv_bfloat16 g_Wth[3][DM * DM];
__device__ __align__(16) __nv_bfloat16 g_Wtl[3][DM * DM];

// ================= PTX helpers =================
__device__ __forceinline__ uint32_t smem_u32(const void* p) {
    uint32_t a;
    asm("{ .reg .u64 t; cvta.to.shared.u64 t, %1; cvt.u32.u64 %0, t; }"
        : "=r"(a) : "l"(p));
    return a;
}
#define SWZ128(off)   ((off) ^ (((off) >> 3) & 0x70))

#define CP_ASYNC16(dst, src) \
    asm volatile("cp.async.cg.shared.global [%0], [%1], 16;" :: "r"(dst), "l"(src))
#define CP_COMMIT() asm volatile("cp.async.commit_group;" ::: "memory")
#define CP_WAIT(n)  asm volatile("cp.async.wait_group %0;" :: "n"(n) : "memory")

__device__ __forceinline__ void ldsm_x4(uint32_t* r, uint32_t addr) {
    asm volatile("ldmatrix.sync.aligned.m8n8.x4.shared.b16 {%0,%1,%2,%3}, [%4];"
        : "=r"(r[0]), "=r"(r[1]), "=r"(r[2]), "=r"(r[3]) : "r"(addr));
}
__device__ __forceinline__ void mma16816(float* d, const uint32_t* a,
                                         const uint32_t* b, const float* c) {
    asm volatile(
        "mma.sync.aligned.m16n8k16.row.col.f32.bf16.bf16.f32 "
        "{%0,%1,%2,%3},{%4,%5,%6,%7},{%8,%9},{%10,%11,%12,%13};"
        : "=f"(d[0]), "=f"(d[1]), "=f"(d[2]), "=f"(d[3])
        : "r"(a[0]), "r"(a[1]), "r"(a[2]), "r"(a[3]),
          "r"(b[0]), "r"(b[1]),
          "f"(c[0]), "f"(c[1]), "f"(c[2]), "f"(c[3]));
}

__device__ __forceinline__ void split8(const float* xs, __nv_bfloat16* h,
                                       __nv_bfloat16* l) {
#pragma unroll
    for (int i = 0; i < 8; i++) {
        __nv_bfloat16 hb = __float2bfloat16(xs[i]);
        h[i] = hb;
        l[i] = __float2bfloat16(xs[i] - __bfloat162float(hb));
    }
}
__device__ __forceinline__ uint32_t pack2(float a, float b) {
    __nv_bfloat162 v;
    v.x = __float2bfloat16(a);
    v.y = __float2bfloat16(b);
    return *(uint32_t*)&v;
}

#define T_AH 0
#define T_AL 16384
#define T_WH 32768
#define T_WL 49152
#define STAGE_SZ 65536
#define OFF_BIAS 131072
#define DYN_SMEM (131072 + 1024)

// att_mma smem offsets
#define A_QH 0
#define A_QL 8192
#define A_KH 16384
#define A_KL 24576
#define A_VH 32768
#define A_VL 40960
#define A_TOP 49152
#define DYN_SMEM_ATT (49152 + 256)

// ---------------- W prep: transpose + split to bf16 hi/lo ----------------
__global__ __launch_bounds__(256) void prep_w(const float* __restrict__ Wq,
                                              const float* __restrict__ Wk,
                                              const float* __restrict__ Wv)
{
    int which = blockIdx.y;
    const float* W = (which == 0) ? Wq : (which == 1) ? Wk : Wv;
    int idx = (blockIdx.x * 256 + threadIdx.x) * 4;
    int n = idx >> 9, k = idx & 511;
#pragma unroll
    for (int i = 0; i < 4; i++) {
        float x = W[(size_t)(k + i) * DM + n];
        __nv_bfloat16 hb = __float2bfloat16(x);
        g_Wth[which][(size_t)n * DM + k + i] = hb;
        g_Wtl[which][(size_t)n * DM + k + i] = __float2bfloat16(x - __bfloat162float(hb));
    }
}

// ---------------- split-bf16 mma.sync GEMM with fused fp32->bf16 A split ----------------
__global__ __launch_bounds__(256) void proj_mma(
    const float* __restrict__ qin, const float* __restrict__ kin,
    const float* __restrict__ vin,
    const float* __restrict__ bq, const float* __restrict__ bk,
    const float* __restrict__ bv)
{
    extern __shared__ char dsm[];
    int which = blockIdx.z;
    float* P = (which == 0) ? g_Q : (which == 1) ? g_K : g_V;
    const float* bias = (which == 0) ? bq : (which == 1) ? bk : bv;
    const float* Afp = (which == 0) ? qin : (which == 1) ? kin : vin;
    const __nv_bfloat16* Wh = g_Wth[which];
    const __nv_bfloat16* Wl = g_Wtl[which];

    uint32_t su = smem_u32(dsm);
    int tid = threadIdx.x;
    int lane = tid & 31, wid = tid >> 5;
    int wm = wid & 3, wn = wid >> 2;
    int m0 = blockIdx.y * 128, n0 = blockIdx.x * 128;

    float* bias_s = (float*)(dsm + OFF_BIAS);
    if (tid < 128) bias_s[tid] = bias[n0 + tid];

    float acc[2][8][4];
#pragma unroll
    for (int a = 0; a < 2; a++)
#pragma unroll
        for (int b = 0; b < 8; b++)
#pragma unroll
            for (int c = 0; c < 4; c++) acc[a][b][c] = 0.f;

    float4 areg[4][2];
    auto ldA = [&](int k0) {
#pragma unroll
        for (int t = 0; t < 4; t++) {
            int idx = tid + 256 * t;
            int r = idx >> 3, c = idx & 7;
            const float* src = Afp + (size_t)(m0 + r) * DM + k0 + c * 8;
            areg[t][0] = *(const float4*)src;
            areg[t][1] = *(const float4*)(src + 4);
        }
    };
    auto stsA = [&](int stage) {
#pragma unroll
        for (int t = 0; t < 4; t++) {
            int idx = tid + 256 * t;
            int r = idx >> 3, c = idx & 7;
            float xs[8] = {areg[t][0].x, areg[t][0].y, areg[t][0].z, areg[t][0].w,
                           areg[t][1].x, areg[t][1].y, areg[t][1].z, areg[t][1].w};
            __align__(16) __nv_bfloat16 h[8], l[8];
            split8(xs, h, l);
            uint32_t sw = SWZ128((uint32_t)(r * 128 + c * 16));
            *(uint4*)(dsm + stage * STAGE_SZ + T_AH + sw) = *(uint4*)h;
            *(uint4*)(dsm + stage * STAGE_SZ + T_AL + sw) = *(uint4*)l;
        }
    };
    auto cpW = [&](int stage, int k0) {
        uint32_t sb = su + stage * STAGE_SZ;
#pragma unroll
        for (int t = 0; t < 4; t++) {
            int idx = tid + 256 * t;
            int r = idx >> 3, c = idx & 7;
            uint32_t sw = SWZ128((uint32_t)(r * 128 + c * 16));
            CP_ASYNC16(sb + T_WH + sw, Wh + (size_t)(n0 + r) * DM + k0 + c * 8);
            CP_ASYNC16(sb + T_WL + sw, Wl + (size_t)(n0 + r) * DM + k0 + c * 8);
        }
        CP_COMMIT();
    };

    ldA(0);
    cpW(0, 0);
    stsA(0);
    ldA(64);

    int a_row = (lane & 15), a_k16 = (lane >> 4) << 4;
    int b_grp = lane >> 3;
    int b_row = ((b_grp >> 1) << 3) + (lane & 7);
    int b_k16 = (b_grp & 1) << 4;

    for (int chunk = 0; chunk < 8; chunk++) {
        if (chunk < 7) cpW((chunk + 1) & 1, (chunk + 1) * 64);
        if (chunk < 7) { CP_WAIT(1); } else { CP_WAIT(0); }
        __syncthreads();

        if (chunk < 7) stsA((chunk + 1) & 1);
        if (chunk < 6) ldA((chunk + 2) * 64);

        uint32_t sb = su + (chunk & 1) * STAGE_SZ;
#pragma unroll
        for (int ks = 0; ks < 4; ks++) {
            uint32_t ah[2][4], al[2][4], bh[16], bl[16];
#pragma unroll
            for (int mf = 0; mf < 2; mf++) {
                int row = wm * 32 + mf * 16 + a_row;
                uint32_t off = SWZ128((uint32_t)(row * 128 + ks * 32 + a_k16));
                ldsm_x4(ah[mf], sb + T_AH + off);
                ldsm_x4(al[mf], sb + T_AL + off);
            }
#pragma unroll
            for (int g2 = 0; g2 < 4; g2++) {
                int row = wn * 64 + g2 * 16 + b_row;
                uint32_t off = SWZ128((uint32_t)(row * 128 + ks * 32 + b_k16));
                ldsm_x4(&bh[g2 * 4], sb + T_WH + off);
                ldsm_x4(&bl[g2 * 4], sb + T_WL + off);
            }
#pragma unroll
            for (int mf = 0; mf < 2; mf++)
#pragma unroll
                for (int nf = 0; nf < 8; nf++)
                    mma16816(acc[mf][nf], ah[mf], &bh[nf * 2], acc[mf][nf]);
#pragma unroll
            for (int mf = 0; mf < 2; mf++)
#pragma unroll
                for (int nf = 0; nf < 8; nf++)
                    mma16816(acc[mf][nf], ah[mf], &bl[nf * 2], acc[mf][nf]);
#pragma unroll
            for (int mf = 0; mf < 2; mf++)
#pragma unroll
                for (int nf = 0; nf < 8; nf++)
                    mma16816(acc[mf][nf], al[mf], &bh[nf * 2], acc[mf][nf]);
        }
        __syncthreads();
    }

    float* Cs = (float*)dsm;
#pragma unroll
    for (int mf = 0; mf < 2; mf++)
#pragma unroll
        for (int nf = 0; nf < 8; nf++) {
            int r = wm * 32 + mf * 16 + (lane >> 2);
            int col = wn * 64 + nf * 8 + (lane & 3) * 2;
            Cs[r * 132 + col]           = acc[mf][nf][0] + bias_s[col];
            Cs[r * 132 + col + 1]       = acc[mf][nf][1] + bias_s[col + 1];
            Cs[(r + 8) * 132 + col]     = acc[mf][nf][2] + bias_s[col];
            Cs[(r + 8) * 132 + col + 1] = acc[mf][nf][3] + bias_s[col + 1];
        }
    __syncthreads();

    // fused meanV partial: distributed column sums of the V tile
    if (which == 2) {
        int col = tid & 127, half = tid >> 7;
        float s = 0.f;
#pragma unroll 8
        for (int r = 0; r < 64; r++) s += Cs[(half * 64 + r) * 132 + col];
        float* hs = (float*)(dsm + OFF_BIAS);   // bias dead; reuse
        if (half == 1) hs[col] = s;
        __syncthreads();
        if (half == 0) {
            int b = m0 >> 12, mt = (m0 >> 7) & 31;
            g_mvp[mt][b * DM + n0 + col] = s + hs[col];
        }
    }

#pragma unroll
    for (int it = 0; it < 16; it++) {
        int idx = tid + it * 256;
        int row = idx >> 5, c4 = idx & 31;
        int m = m0 + row;
        int b = m >> 12, l = m & (LL - 1);
        int n = n0 + c4 * 4;
        int h = n >> 6, d = n & 63;
        float4 v;
        v.x = Cs[row * 132 + c4 * 4 + 0];
        v.y = Cs[row * 132 + c4 * 4 + 1];
        v.z = Cs[row * 132 + c4 * 4 + 2];
        v.w = Cs[row * 132 + c4 * 4 + 3];
        *(float4*)&P[((size_t)(b * HH + h) * LL + l) * DD + d] = v;
    }
}

// ---------------- sampled scoring via MMA: 128x48x64 per block ----------------
__global__ __launch_bounds__(128) void score_mma(const int* __restrict__ sidx)
{
    __shared__ __align__(16) char AH[16384];
    __shared__ __align__(16) char AL[16384];
    __shared__ __align__(16) char BHs[6144];
    __shared__ __align__(16) char BLs[6144];
    __shared__ int ssi[UU];
    int bh = blockIdx.x, m0 = blockIdx.y * 128;
    int tid = threadIdx.x, lane = tid & 31, wm = tid >> 5;

    if (tid < UU) ssi[tid] = sidx[tid];
    for (int i = tid; i < 6144 / 16; i += 128) {
        ((uint4*)BHs)[i] = make_uint4(0, 0, 0, 0);
        ((uint4*)BLs)[i] = make_uint4(0, 0, 0, 0);
    }
    __syncthreads();

    for (int u = tid; u < UU * 8; u += 128) {
        int j = u >> 3, c = u & 7;
        const float* src = g_K + ((size_t)bh * LL + ssi[j]) * DD + c * 8;
        float4 f0 = *(const float4*)src, f1 = *(const float4*)(src + 4);
        float xs[8] = {f0.x, f0.y, f0.z, f0.w, f1.x, f1.y, f1.z, f1.w};
        __align__(16) __nv_bfloat16 h[8], l[8];
        split8(xs, h, l);
        uint32_t sw = SWZ128((uint32_t)(j * 128 + c * 16));
        *(uint4*)(BHs + sw) = *(uint4*)h;
        *(uint4*)(BLs + sw) = *(uint4*)l;
    }
#pragma unroll
    for (int t = 0; t < 8; t++) {
        int idx = tid + 128 * t;
        int r = idx >> 3, c = idx & 7;
        const float* src = g_Q + ((size_t)bh * LL + m0 + r) * DD + c * 8;
        float4 f0 = *(const float4*)src, f1 = *(const float4*)(src + 4);
        float xs[8] = {f0.x, f0.y, f0.z, f0.w, f1.x, f1.y, f1.z, f1.w};
        __align__(16) __nv_bfloat16 h[8], l[8];
        split8(xs, h, l);
        uint32_t sw = SWZ128((uint32_t)(r * 128 + c * 16));
        *(uint4*)(AH + sw) = *(uint4*)h;
        *(uint4*)(AL + sw) = *(uint4*)l;
    }
    __syncthreads();

    float acc[2][6][4];
#pragma unroll
    for (int a = 0; a < 2; a++)
#pragma unroll
        for (int b = 0; b < 6; b++)
#pragma unroll
            for (int c = 0; c < 4; c++) acc[a][b][c] = 0.f;

    uint32_t suA_h = smem_u32(AH), suA_l = smem_u32(AL);
    uint32_t suB_h = smem_u32(BHs), suB_l = smem_u32(BLs);
    int a_row = (lane & 15), a_k16 = (lane >> 4) << 4;
    int b_grp = lane >> 3;
    int b_row = ((b_grp >> 1) << 3) + (lane & 7);
    int b_k16 = (b_grp & 1) << 4;

#pragma unroll
    for (int ks = 0; ks < 4; ks++) {
        uint32_t ah[2][4], al[2][4], bhf[12], blf[12];
#pragma unroll
        for (int mf = 0; mf < 2; mf++) {
            int row = wm * 32 + mf * 16 + a_row;
            uint32_t off = SWZ128((uint32_t)(row * 128 + ks * 32 + a_k16));
            ldsm_x4(ah[mf], suA_h + off);
            ldsm_x4(al[mf], suA_l + off);
        }
#pragma unroll
        for (int g2 = 0; g2 < 3; g2++) {
            int row = g2 * 16 + b_row;
            uint32_t off = SWZ128((uint32_t)(row * 128 + ks * 32 + b_k16));
            ldsm_x4(&bhf[g2 * 4], suB_h + off);
            ldsm_x4(&blf[g2 * 4], suB_l + off);
        }
#pragma unroll
        for (int mf = 0; mf < 2; mf++)
#pragma unroll
            for (int nf = 0; nf < 6; nf++)
                mma16816(acc[mf][nf], ah[mf], &bhf[nf * 2], acc[mf][nf]);
#pragma unroll
        for (int mf = 0; mf < 2; mf++)
#pragma unroll
            for (int nf = 0; nf < 6; nf++)
                mma16816(acc[mf][nf], ah[mf], &blf[nf * 2], acc[mf][nf]);
#pragma unroll
        for (int mf = 0; mf < 2; mf++)
#pragma unroll
            for (int nf = 0; nf < 6; nf++)
                mma16816(acc[mf][nf], al[mf], &bhf[nf * 2], acc[mf][nf]);
    }

    int cbase = (lane & 3) * 2;
#pragma unroll
    for (int mf = 0; mf < 2; mf++) {
        float mx0 = -1e30f, sm0 = 0.f, mx1 = -1e30f, sm1 = 0.f;
#pragma unroll
        for (int nf = 0; nf < 6; nf++) {
            int c0 = nf * 8 + cbase, c1 = c0 + 1;
            if (c0 < UU) { mx0 = fmaxf(mx0, acc[mf][nf][0]); sm0 += acc[mf][nf][0]; }
            if (c1 < UU) { mx0 = fmaxf(mx0, acc[mf][nf][1]); sm0 += acc[mf][nf][1]; }
            if (c0 < UU) { mx1 = fmaxf(mx1, acc[mf][nf][2]); sm1 += acc[mf][nf][2]; }
            if (c1 < UU) { mx1 = fmaxf(mx1, acc[mf][nf][3]); sm1 += acc[mf][nf][3]; }
        }
#pragma unroll
        for (int off = 1; off < 4; off <<= 1) {
            mx0 = fmaxf(mx0, __shfl_xor_sync(0xffffffffu, mx0, off));
            sm0 += __shfl_xor_sync(0xffffffffu, sm0, off);
            mx1 = fmaxf(mx1, __shfl_xor_sync(0xffffffffu, mx1, off));
            sm1 += __shfl_xor_sync(0xffffffffu, sm1, off);
        }
        if ((lane & 3) == 0) {
            int r = wm * 32 + mf * 16 + (lane >> 2);
            g_M[(size_t)bh * LL + m0 + r]     = (mx0 - sm0 * (1.f / UU)) * SCALE;
            g_M[(size_t)bh * LL + m0 + r + 8] = (mx1 - sm1 * (1.f / UU)) * SCALE;
        }
    }
}

// ---------------- top-45 via radix select ----------------
__global__ __launch_bounds__(256) void topk_kernel()
{
    __shared__ uint32_t uvals[LL];
    __shared__ int histw[8][256];
    __shared__ int scan[256];
    __shared__ int sel_byte, new_k;
    __shared__ int cnt_g, cnt_e;
    __shared__ int eq[256];
    int bh = blockIdx.x, tid = threadIdx.x;
    int w = tid >> 5;

    for (int i = tid; i < LL; i += 256) {
        uint32_t u = __float_as_uint(g_M[(size_t)bh * LL + i]);
        uvals[i] = (u & 0x80000000u) ? ~u : (u | 0x80000000u);
    }

    uint32_t prefix = 0, mask = 0;
    int k = UU;
    for (int pass = 0; pass < 4; pass++) {
        int shift = 24 - pass * 8;
#pragma unroll
        for (int ww = 0; ww < 8; ww++) histw[ww][tid] = 0;
        __syncthreads();
        for (int i = tid; i < LL; i += 256) {
            uint32_t u = uvals[i];
            if ((u & mask) == prefix)
                atomicAdd(&histw[w][(u >> shift) & 255], 1);
        }
        __syncthreads();
        int c = 0;
#pragma unroll
        for (int ww = 0; ww < 8; ww++) c += histw[ww][tid];
        scan[tid] = c;
        __syncthreads();
#pragma unroll
        for (int off = 1; off < 256; off <<= 1) {
            int v = (tid + off < 256) ? scan[tid + off] : 0;
            __syncthreads();
            scan[tid] += v;
            __syncthreads();
        }
        {
            int snext = (tid < 255) ? scan[tid + 1] : 0;
            if (scan[tid] >= k && snext < k) {
                sel_byte = tid;
                new_k = k - snext;
            }
        }
        __syncthreads();
        prefix |= ((uint32_t)sel_byte << shift);
        mask |= (255u << shift);
        k = new_k;
        __syncthreads();
    }
    uint32_t T = prefix;

    if (tid == 0) { cnt_g = 0; cnt_e = 0; }
    __syncthreads();
    for (int i = tid; i < LL; i += 256) {
        uint32_t u = uvals[i];
        if (u > T) {
            int p = atomicAdd(&cnt_g, 1);
            g_top[bh * UU + p] = i;
        } else if (u == T) {
            int p = atomicAdd(&cnt_e, 1);
            if (p < 256) eq[p] = i;
        }
    }
    __syncthreads();
    int ng = cnt_g;
    int need = UU - ng;
    if (tid == 0 && need > 0) {
        if (cnt_e <= 256) {
            int ec = cnt_e;
            for (int s = 0; s < need; s++) {
                int best = s;
                for (int j = s + 1; j < ec; j++)
                    if (eq[j] < eq[best]) best = j;
                int t = eq[s]; eq[s] = eq[best]; eq[best] = t;
                g_top[bh * UU + ng + s] = eq[s];
            }
        } else {
            int got = 0;
            for (int i = 0; i < LL && got < need; i++)
                if (uvals[i] == T) { g_top[bh * UU + ng + got] = i; got++; }
        }
    }
}

// ---------------- hit map ----------------
__global__ __launch_bounds__(256) void zero_hits()
{
    int i = blockIdx.x * 256 + threadIdx.x;
    g_hitcnt[i] = 0;
}
__global__ __launch_bounds__(64) void build_hits()
{
    int bh = blockIdx.x, tid = threadIdx.x;
    if (tid < UU) {
        int b = bh >> 3, h = bh & 7;
        int t = g_top[bh * UU + tid];
        int p = atomicAdd(&g_hitcnt[b * LL + t], 1);
        g_hitlist[(b * LL + t) * 8 + p] = (h << 8) | tid;
    }
}

// ---------------- meanV reduce from proj partials ----------------
__global__ __launch_bounds__(64) void mv_reduce()
{
    int bh = blockIdx.x, d = threadIdx.x;
    int b = bh >> 3, h = bh & 7;
    float s = 0.f;
#pragma unroll
    for (int p = 0; p < 32; p++) s += g_mvp[p][b * DM + h * 64 + d];
    g_meanV[bh * DD + d] = s * (1.f / LL);
}

// ---------------- base row per batch ----------------
__global__ __launch_bounds__(512) void base_kernel(const float* __restrict__ Wo,
                                                   const float* __restrict__ bo)
{
    int b = blockIdx.x, c = threadIdx.x;
    float acc = bo[c];
    const float* mv = g_meanV + b * DM;
    for (int k = 0; k < DM; k++) acc += mv[k] * Wo[(size_t)k * DM + c];
    g_base[b * DM + c] = acc;
}

// ---------------- flash attention via MMA, split over NCH chunks ----------------
__global__ __launch_bounds__(128) void att_mma()
{
    extern __shared__ char sm[];
    int bh = blockIdx.x, ch = blockIdx.y;
    int tid = threadIdx.x, lane = tid & 31, w = tid >> 5;
    int* tops = (int*)(sm + A_TOP);

    if (tid < UU) tops[tid] = g_top[bh * UU + tid];
    for (int i = tid; i < 1024; i += 128) {
        ((uint4*)(sm + A_QH))[i] = make_uint4(0, 0, 0, 0);
        ((uint4*)(sm + A_QL))[i] = make_uint4(0, 0, 0, 0);
    }
    __syncthreads();
    for (int u = tid; u < UU * 8; u += 128) {
        int j = u >> 3, c = u & 7;
        const float* src = g_Q + ((size_t)bh * LL + tops[j]) * DD + c * 8;
        float4 f0 = *(const float4*)src, f1 = *(const float4*)(src + 4);
        float xs[8] = {f0.x, f0.y, f0.z, f0.w, f1.x, f1.y, f1.z, f1.w};
        __align__(16) __nv_bfloat16 h[8], l[8];
        split8(xs, h, l);
        uint32_t sw = SWZ128((uint32_t)(j * 128 + c * 16));
        *(uint4*)(sm + A_QH + sw) = *(uint4*)h;
        *(uint4*)(sm + A_QL + sw) = *(uint4*)l;
    }
    __syncthreads();

    uint32_t su = smem_u32(sm);
    int a_row = (lane & 15), a_k16 = (lane >> 4) << 4;
    int b_grp = lane >> 3;
    int b_row = ((b_grp >> 1) << 3) + (lane & 7);
    int b_k16 = (b_grp & 1) << 4;

    uint32_t qah[4][4], qal[4][4];
#pragma unroll
    for (int ks = 0; ks < 4; ks++) {
        int row = w * 16 + a_row;
        uint32_t off = SWZ128((uint32_t)(row * 128 + ks * 32 + a_k16));
        ldsm_x4(qah[ks], su + A_QH + off);
        ldsm_x4(qal[ks], su + A_QL + off);
    }

    float mrow[2] = {-1e30f, -1e30f};
    float lsum[2] = {0.f, 0.f};
    float oacc[8][4];
#pragma unroll
    for (int nf = 0; nf < 8; nf++)
#pragma unroll
        for (int c = 0; c < 4; c++) oacc[nf][c] = 0.f;

    int key0 = ch * CHUNK;
    for (int t0 = 0; t0 < CHUNK; t0 += 64) {
        __syncthreads();
        for (int i = tid; i < 1024; i += 128) {
            int r = i >> 4, c4 = i & 15;
            const float* ks_ = g_K + ((size_t)bh * LL + key0 + t0 + r) * DD + c4 * 4;
            float4 kv = *(const float4*)ks_;
            float xk[4] = {kv.x, kv.y, kv.z, kv.w};
            __nv_bfloat16 h4[4], l4[4];
#pragma unroll
            for (int q2 = 0; q2 < 4; q2++) {
                __nv_bfloat16 hb = __float2bfloat16(xk[q2]);
                h4[q2] = hb;
                l4[q2] = __float2bfloat16(xk[q2] - __bfloat162float(hb));
            }
            uint32_t sw = SWZ128((uint32_t)(r * 128 + c4 * 8));
            *(uint2*)(sm + A_KH + sw) = *(uint2*)h4;
            *(uint2*)(sm + A_KL + sw) = *(uint2*)l4;

            const float* vs_ = g_V + ((size_t)bh * LL + key0 + t0 + r) * DD + c4 * 4;
            float4 vv = *(const float4*)vs_;
            float xv[4] = {vv.x, vv.y, vv.z, vv.w};
#pragma unroll
            for (int q2 = 0; q2 < 4; q2++) {
                int d = c4 * 4 + q2;
                __nv_bfloat16 hb = __float2bfloat16(xv[q2]);
                __nv_bfloat16 lb = __float2bfloat16(xv[q2] - __bfloat162float(hb));
                uint32_t swv = SWZ128((uint32_t)(d * 128 + r * 2));
                *(__nv_bfloat16*)(sm + A_VH + swv) = hb;
                *(__nv_bfloat16*)(sm + A_VL + swv) = lb;
            }
        }
        __syncthreads();

        float sacc[8][4];
#pragma unroll
        for (int nf = 0; nf < 8; nf++)
#pragma unroll
            for (int c = 0; c < 4; c++) sacc[nf][c] = 0.f;
#pragma unroll
        for (int ks = 0; ks < 4; ks++) {
            uint32_t kbh[16], kbl[16];
#pragma unroll
            for (int g2 = 0; g2 < 4; g2++) {
                int row = g2 * 16 + b_row;
                uint32_t off = SWZ128((uint32_t)(row * 128 + ks * 32 + b_k16));
                ldsm_x4(&kbh[g2 * 4], su + A_KH + off);
                ldsm_x4(&kbl[g2 * 4], su + A_KL + off);
            }
#pragma unroll
            for (int nf = 0; nf < 8; nf++)
                mma16816(sacc[nf], qah[ks], &kbh[nf * 2], sacc[nf]);
#pragma unroll
            for (int nf = 0; nf < 8; nf++)
                mma16816(sacc[nf], qah[ks], &kbl[nf * 2], sacc[nf]);
#pragma unroll
            for (int nf = 0; nf < 8; nf++)
                mma16816(sacc[nf], qal[ks], &kbh[nf * 2], sacc[nf]);
        }
#pragma unroll
        for (int nf = 0; nf < 8; nf++)
#pragma unroll
            for (int c = 0; c < 4; c++) sacc[nf][c] *= SCALE;
        float tmax0 = -1e30f, tmax1 = -1e30f;
#pragma unroll
        for (int nf = 0; nf < 8; nf++) {
            tmax0 = fmaxf(tmax0, fmaxf(sacc[nf][0], sacc[nf][1]));
            tmax1 = fmaxf(tmax1, fmaxf(sacc[nf][2], sacc[nf][3]));
        }
#pragma unroll
        for (int off = 1; off < 4; off <<= 1) {
            tmax0 = fmaxf(tmax0, __shfl_xor_sync(0xffffffffu, tmax0, off));
            tmax1 = fmaxf(tmax1, __shfl_xor_sync(0xffffffffu, tmax1, off));
        }
        float mn0 = fmaxf(mrow[0], tmax0), mn1 = fmaxf(mrow[1], tmax1);
        float al0 = __expf(mrow[0] - mn0), al1 = __expf(mrow[1] - mn1);
        float rs0 = 0.f, rs1 = 0.f;
#pragma unroll
        for (int nf = 0; nf < 8; nf++) {
            sacc[nf][0] = __expf(sacc[nf][0] - mn0);
            sacc[nf][1] = __expf(sacc[nf][1] - mn0);
            sacc[nf][2] = __expf(sacc[nf][2] - mn1);
            sacc[nf][3] = __expf(sacc[nf][3] - mn1);
            rs0 += sacc[nf][0] + sacc[nf][1];
            rs1 += sacc[nf][2] + sacc[nf][3];
        }
#pragma unroll
        for (int off = 1; off < 4; off <<= 1) {
            rs0 += __shfl_xor_sync(0xffffffffu, rs0, off);
            rs1 += __shfl_xor_sync(0xffffffffu, rs1, off);
        }
        lsum[0] = lsum[0] * al0 + rs0;
        lsum[1] = lsum[1] * al1 + rs1;
        mrow[0] = mn0;
        mrow[1] = mn1;
#pragma unroll
        for (int nf = 0; nf < 8; nf++) {
            oacc[nf][0] *= al0; oacc[nf][1] *= al0;
            oacc[nf][2] *= al1; oacc[nf][3] *= al1;
        }
#pragma unroll
        for (int ks = 0; ks < 4; ks++) {
            uint32_t pah[4], pal[4];
            {
                float p0 = sacc[2 * ks][0],     p1 = sacc[2 * ks][1];
                float p2 = sacc[2 * ks][2],     p3 = sacc[2 * ks][3];
                float p4 = sacc[2 * ks + 1][0], p5 = sacc[2 * ks + 1][1];
                float p6 = sacc[2 * ks + 1][2], p7 = sacc[2 * ks + 1][3];
                float h0 = __bfloat162float(__float2bfloat16(p0));
                float h1 = __bfloat162float(__float2bfloat16(p1));
                float h2 = __bfloat162float(__float2bfloat16(p2));
                float h3 = __bfloat162float(__float2bfloat16(p3));
                float h4 = __bfloat162float(__float2bfloat16(p4));
                float h5 = __bfloat162float(__float2bfloat16(p5));
                float h6 = __bfloat162float(__float2bfloat16(p6));
                float h7 = __bfloat162float(__float2bfloat16(p7));
                pah[0] = pack2(p0, p1); pah[1] = pack2(p2, p3);
                pah[2] = pack2(p4, p5); pah[3] = pack2(p6, p7);
                pal[0] = pack2(p0 - h0, p1 - h1); pal[1] = pack2(p2 - h2, p3 - h3);
                pal[2] = pack2(p4 - h4, p5 - h5); pal[3] = pack2(p6 - h6, p7 - h7);
            }
            uint32_t vbh[16], vbl[16];
#pragma unroll
            for (int g2 = 0; g2 < 4; g2++) {
                int row = g2 * 16 + b_row;
                uint32_t off = SWZ128((uint32_t)(row * 128 + ks * 32 + b_k16));
                ldsm_x4(&vbh[g2 * 4], su + A_VH + off);
                ldsm_x4(&vbl[g2 * 4], su + A_VL + off);
            }
#pragma unroll
            for (int nf = 0; nf < 8; nf++)
                mma16816(oacc[nf], pah, &vbh[nf * 2], oacc[nf]);
#pragma unroll
            for (int nf = 0; nf < 8; nf++)
                mma16816(oacc[nf], pah, &vbl[nf * 2], oacc[nf]);
#pragma unroll
            for (int nf = 0; nf < 8; nf++)
                mma16816(oacc[nf], pal, &vbh[nf * 2], oacc[nf]);
        }
    }

    int r0 = w * 16 + (lane >> 2);
    int r1 = r0 + 8;
    int cb = (lane & 3) * 2;
    if (r0 < UU) {
        int idx = (bh * NCH + ch) * UU + r0;
        if ((lane & 3) == 0) { g_pm[idx] = mrow[0]; g_pl[idx] = lsum[0]; }
        float* pa = g_pacc + (size_t)idx * DD;
#pragma unroll
        for (int nf = 0; nf < 8; nf++) {
            pa[nf * 8 + cb]     = oacc[nf][0];
            pa[nf * 8 + cb + 1] = oacc[nf][1];
        }
    }
    if (r1 < UU) {
        int idx = (bh * NCH + ch) * UU + r1;
        if ((lane & 3) == 0) { g_pm[idx] = mrow[1]; g_pl[idx] = lsum[1]; }
        float* pa = g_pacc + (size_t)idx * DD;
#pragma unroll
        for (int nf = 0; nf < 8; nf++) {
            pa[nf * 8 + cb]     = oacc[nf][2];
            pa[nf * 8 + cb + 1] = oacc[nf][3];
        }
    }
}

// ---------------- merge split-L partials ----------------
__global__ __launch_bounds__(64) void combine_kernel()
{
    int r = blockIdx.x;
    int d = threadIdx.x;
    int bh = r / UU, q = r % UU;
    float M = -1e30f;
#pragma unroll
    for (int c = 0; c < NCH; c++)
        M = fmaxf(M, g_pm[(bh * NCH + c) * UU + q]);
    float Ltot = 0.f, acc = 0.f;
#pragma unroll
    for (int c = 0; c < NCH; c++) {
        int idx = (bh * NCH + c) * UU + q;
        float e = __expf(g_pm[idx] - M);
        Ltot += g_pl[idx] * e;
        acc  += e * g_pacc[(size_t)idx * DD + d];
    }
    g_attn[(size_t)(bh * UU + q) * DD + d] = acc / Ltot;
}

// ---------------- final output: hit-list driven (round-15 version) ----------------
__global__ __launch_bounds__(128) void final_kernel(const float* __restrict__ Wo,
                                                    float* __restrict__ out)
{
    __shared__ float delta[64];
    __shared__ int hits[8];
    int qrow = blockIdx.x, b = blockIdx.y;
    int tid = threadIdx.x;
    int c0 = tid * 4;

    int cnt = g_hitcnt[b * LL + qrow];
    float4 acc = *(const float4*)&g_base[b * DM + c0];

    if (cnt > 0) {
        if (tid < cnt) hits[tid] = g_hitlist[(b * LL + qrow) * 8 + tid];
        __syncthreads();
        if (tid == 0) {
            for (int s = 1; s < cnt; s++) {
                int v = hits[s], j2 = s;
                while (j2 > 0 && hits[j2 - 1] > v) { hits[j2] = hits[j2 - 1]; j2--; }
                hits[j2] = v;
            }
        }
        __syncthreads();
        for (int i = 0; i < cnt; i++) {
            int e = hits[i];
            int h = e >> 8, j = e & 255;
            if (tid < 64)
                delta[tid] = g_attn[((size_t)(b * HH + h) * UU + j) * DD + tid] -
                             g_meanV[(b * HH + h) * DD + tid];
            __syncthreads();
#pragma unroll 4
            for (int d = 0; d < 64; d++) {
                float dv = delta[d];
                float4 w = *(const float4*)&Wo[(size_t)(h * 64 + d) * DM + c0];
                acc.x += dv * w.x; acc.y += dv * w.y;
                acc.z += dv * w.z; acc.w += dv * w.w;
            }
            __syncthreads();
        }
    }
    *(float4*)&out[((size_t)b * LL + qrow) * DM + c0] = acc;
}

// ---------------- launcher ----------------
extern "C" void kernel_launch(void* const* d_in, const int* in_sizes, int n_in,
                              void* d_out, int out_size)
{
    const float* queries = (const float*)d_in[0];
    const float* keys    = (const float*)d_in[1];
    const float* values  = (const float*)d_in[2];
    const int*   sidx    = (const int*)d_in[3];
    const float* Wq = (const float*)d_in[4];
    const float* bq = (const float*)d_in[5];
    const float* Wk = (const float*)d_in[6];
    const float* bk = (const float*)d_in[7];
    const float* Wv = (const float*)d_in[8];
    const float* bv = (const float*)d_in[9];
    const float* Wo = (const float*)d_in[10];
    const float* bo = (const float*)d_in[11];
    float* out = (float*)d_out;

    static int smem_set = 0;
    if (!smem_set) {
        cudaFuncSetAttribute(proj_mma, cudaFuncAttributeMaxDynamicSharedMemorySize, DYN_SMEM);
        cudaFuncSetAttribute(att_mma, cudaFuncAttributeMaxDynamicSharedMemorySize, DYN_SMEM_ATT);
        smem_set = 1;
    }

    prep_w<<<dim3(256, 3), 256>>>(Wq, Wk, Wv);
    zero_hits<<<BB * LL / 256, 256>>>();

    proj_mma<<<dim3(DM / 128, BL / 128, 3), 256, DYN_SMEM>>>(
        queries, keys, values, bq, bk, bv);

    mv_reduce<<<BB * HH, 64>>>();
    score_mma<<<dim3(BB * HH, LL / 128), 128>>>(sidx);
    topk_kernel<<<BB * HH, 256>>>();
    build_hits<<<BB * HH, 64>>>();
    base_kernel<<<BB, 512>>>(Wo, bo);
    att_mma<<<dim3(BB * HH, NCH), 128, DYN_SMEM_ATT>>>();
    combine_kernel<<<BB * HH * UU, 64>>>();
    final_kernel<<<dim3(LL, BB), 128>>>(Wo, out);
}